// round 12
// baseline (speedup 1.0000x reference)
#include <cuda_runtime.h>
#include <cuda_bf16.h>
#include <cstdint>

// Problem constants (fixed shapes)
#define L_TOK   4096
#define D_HID   768
#define H_HEAD  12
#define DH      64
#define M2      2048          // L/2
#define OUT_TOK 2049          // 1 unmerged + 2048 dst
#define NBLK    256           // argmax grid size (16x16)

// ---------------- device scratch (no allocations allowed) ----------------
__device__ float              g_m[L_TOK * DH];      // normalized metric, 1 MB
__device__ unsigned long long g_best[M2];           // packed (score, ~col)
__device__ int                g_cnt[M2];            // #srcs per dst
__device__ int                g_off[M2];            // CSR offsets
__device__ int                g_list[M2];           // src rows grouped by dst
__device__ int                g_done;               // argmax completion counter

__device__ __forceinline__ unsigned sortable_f32(float f) {
    unsigned u = __float_as_uint(f);
    return (u & 0x80000000u) ? ~u : (u | 0x80000000u);
}
__device__ __forceinline__ unsigned long long pack2(float x) {
    unsigned long long r;
    asm("mov.b64 %0, {%1, %1};" : "=l"(r) : "f"(x));
    return r;
}
__device__ __forceinline__ void ffma2(unsigned long long& d,
                                      unsigned long long a,
                                      unsigned long long b) {
    asm("fma.rn.f32x2 %0, %1, %2, %0;" : "+l"(d) : "l"(a), "l"(b));
}

// ------------------------------------------------------------------------
// K1: metric = mean over heads of key_layer[0], L2-normalized per row.
//     Also initializes g_best and g_done (deterministic per launch).
// grid: 512 x 256 (one warp per row)
// ------------------------------------------------------------------------
__global__ void k_metric(const float* __restrict__ key) {
    int gtid = blockIdx.x * blockDim.x + threadIdx.x;
    if (gtid < M2) g_best[gtid] = 0ull;
    if (gtid == 0) g_done = 0;

    int row  = gtid >> 5;
    int lane = threadIdx.x & 31;
    if (row < L_TOK) {
        float v0 = 0.f, v1 = 0.f;
        const float* base = key + (size_t)row * DH;
        #pragma unroll
        for (int h = 0; h < H_HEAD; h++) {
            v0 += base[(size_t)h * L_TOK * DH + lane];
            v1 += base[(size_t)h * L_TOK * DH + lane + 32];
        }
        const float invH = 1.0f / (float)H_HEAD;
        v0 *= invH; v1 *= invH;
        float ss = v0 * v0 + v1 * v1;
        #pragma unroll
        for (int o = 16; o; o >>= 1) ss += __shfl_xor_sync(0xffffffffu, ss, o);
        float r = rsqrtf(ss);
        r = r * (1.5f - 0.5f * ss * r * r);   // one Newton step
        g_m[row * DH + lane]      = v0 * r;
        g_m[row * DH + lane + 32] = v1 * r;
    }
}

// ------------------------------------------------------------------------
// K2: argmax_j dot(a_i, b_j) — 2048x2048x64 fp32 GEMM with FFMA2,
// 128x128 tile, 8x8 microtile, 256 threads, 64 KB dynamic smem.
// LAST CTA (fence+counter) additionally builds the CSR (counts/offsets/
// list) in its smem, replacing the separate k_build launch.
// grid: (16,16)
// ------------------------------------------------------------------------
#define BM 128
__global__ __launch_bounds__(256) void k_argmax() {
    extern __shared__ float smem[];
    float* As = smem;              // [64][128] K-major
    float* Bs = smem + 64 * BM;

    int tid = threadIdx.x;
    int tx  = tid & 15;
    int ty  = tid >> 4;

    int aRow0 = blockIdx.y * BM;
    int bRow0 = blockIdx.x * BM;

    // Load tiles, transposing to K-major. 8 float4 per thread per matrix.
    int lm  = tid & 31;
    int kq8 = tid >> 5;
    #pragma unroll
    for (int it = 0; it < 4; it++) {
        int m = it * 32 + lm;
        const float* arow = &g_m[(size_t)(2 * (aRow0 + m)) * DH];
        const float* brow = &g_m[(size_t)(2 * (bRow0 + m) + 1) * DH];
        #pragma unroll
        for (int half = 0; half < 2; half++) {
            int kq = kq8 + half * 8;
            float4 va = *(const float4*)&arow[kq * 4];
            float4 vb = *(const float4*)&brow[kq * 4];
            As[(kq * 4 + 0) * BM + m] = va.x;
            As[(kq * 4 + 1) * BM + m] = va.y;
            As[(kq * 4 + 2) * BM + m] = va.z;
            As[(kq * 4 + 3) * BM + m] = va.w;
            Bs[(kq * 4 + 0) * BM + m] = vb.x;
            Bs[(kq * 4 + 1) * BM + m] = vb.y;
            Bs[(kq * 4 + 2) * BM + m] = vb.z;
            Bs[(kq * 4 + 3) * BM + m] = vb.w;
        }
    }
    __syncthreads();

    unsigned long long acc2[8][4];
    #pragma unroll
    for (int r = 0; r < 8; r++)
        #pragma unroll
        for (int c = 0; c < 4; c++) acc2[r][c] = 0ull;

    #pragma unroll 8
    for (int k = 0; k < 64; k++) {
        float4 a0 = *(const float4*)&As[k * BM + ty * 8];
        float4 a1 = *(const float4*)&As[k * BM + ty * 8 + 4];
        ulonglong2 b01 = *(const ulonglong2*)&Bs[k * BM + tx * 8];
        ulonglong2 b23 = *(const ulonglong2*)&Bs[k * BM + tx * 8 + 4];
        unsigned long long ap[8];
        ap[0] = pack2(a0.x); ap[1] = pack2(a0.y);
        ap[2] = pack2(a0.z); ap[3] = pack2(a0.w);
        ap[4] = pack2(a1.x); ap[5] = pack2(a1.y);
        ap[6] = pack2(a1.z); ap[7] = pack2(a1.w);
        #pragma unroll
        for (int r = 0; r < 8; r++) {
            ffma2(acc2[r][0], ap[r], b01.x);
            ffma2(acc2[r][1], ap[r], b01.y);
            ffma2(acc2[r][2], ap[r], b23.x);
            ffma2(acc2[r][3], ap[r], b23.y);
        }
    }

    // Argmax epilogue
    #pragma unroll
    for (int r = 0; r < 8; r++) {
        int row = aRow0 + ty * 8 + r;
        unsigned long long key = 0ull;
        #pragma unroll
        for (int c2 = 0; c2 < 4; c2++) {
            unsigned lo, hi;
            asm("mov.b64 {%0, %1}, %2;" : "=r"(lo), "=r"(hi) : "l"(acc2[r][c2]));
            float s0 = __uint_as_float(lo), s1 = __uint_as_float(hi);
            int col0 = bRow0 + tx * 8 + 2 * c2;
            unsigned long long k0 =
                ((unsigned long long)sortable_f32(s0) << 32) | (unsigned)(~(unsigned)col0);
            unsigned long long k1 =
                ((unsigned long long)sortable_f32(s1) << 32) | (unsigned)(~(unsigned)(col0 + 1));
            if (k0 > key) key = k0;
            if (k1 > key) key = k1;
        }
        #pragma unroll
        for (int o = 8; o; o >>= 1) {
            unsigned long long other = __shfl_down_sync(0xffffffffu, key, o, 16);
            key = (other > key) ? other : key;
        }
        if (tx == 0) atomicMax(&g_best[row], key);
    }

    // ---- last-CTA CSR build (replaces k_build) ----
    __syncthreads();
    __shared__ int s_last;
    if (tid == 0) {
        __threadfence();                           // publish g_best writes
        s_last = (atomicAdd(&g_done, 1) == NBLK - 1);
    }
    __syncthreads();
    if (!s_last) return;

    // reuse dynamic smem as int arrays
    int* s_cnt  = (int*)smem;          // 2048
    int* s_off  = s_cnt + M2;          // 2048
    int* s_cur  = s_off + M2;          // 2048
    int* s_wsum = s_cur + M2;          // 8 warp sums

    int lane = tid & 31, wid = tid >> 5;

    for (int i = tid; i < M2; i += 256) s_cnt[i] = 0;
    __syncthreads();

    int d[8];
    #pragma unroll
    for (int q = 0; q < 8; q++) {
        int i = tid * 8 + q;
        d[q] = (int)(~(unsigned)g_best[i]) & (M2 - 1);
        if (i >= 1) atomicAdd(&s_cnt[d[q]], 1);    // src row 0 unmerged
    }
    __syncthreads();

    int c[8], sum = 0;
    #pragma unroll
    for (int q = 0; q < 8; q++) { c[q] = s_cnt[tid * 8 + q]; sum += c[q]; }

    int v = sum;                                   // inclusive warp scan
    #pragma unroll
    for (int o = 1; o < 32; o <<= 1) {
        int n = __shfl_up_sync(0xffffffffu, v, o);
        if (lane >= o) v += n;
    }
    if (lane == 31) s_wsum[wid] = v;
    __syncthreads();
    if (tid == 0) {                                // serial scan of 8 warp sums
        int run = 0;
        #pragma unroll
        for (int w = 0; w < 8; w++) { int x = s_wsum[w]; s_wsum[w] = run; run += x; }
    }
    __syncthreads();
    int run = (v - sum) + s_wsum[wid];             // exclusive prefix for this thread
    #pragma unroll
    for (int q = 0; q < 8; q++) {
        int i = tid * 8 + q;
        s_off[i] = run;
        g_cnt[i] = c[q];
        g_off[i] = run;
        run += c[q];
    }
    __syncthreads();
    for (int i = tid; i < M2; i += 256) s_cur[i] = s_off[i];
    __syncthreads();
    #pragma unroll
    for (int q = 0; q < 8; q++) {
        int i = tid * 8 + q;
        if (i >= 1) { int p = atomicAdd(&s_cur[d[q]], 1); g_list[p] = i; }
    }
}

// ------------------------------------------------------------------------
// K3: gather-merge (best-measured R4 design).
// Block j < 2048: out row 1+j = (dst_row + sum srcs)/(1+cnt).
// Block 2048: unmerged row 0 + attention mask + tome[0].
// grid: 2049 x 192
// ------------------------------------------------------------------------
__global__ __launch_bounds__(192) void k_merge(const float* __restrict__ hidden,
                                               const float* __restrict__ tome,
                                               float* __restrict__ out) {
    float* out_tok  = out;                              // 2049 x 768
    float* out_mask = out + (size_t)OUT_TOK * D_HID;    // 2049
    float* out_tome = out_mask + OUT_TOK;               // 2049
    int b = blockIdx.x, t = threadIdx.x;

    if (b == M2) {   // unmerged row 0, mask, tome[0]
        ((float4*)out_tok)[t] = ((const float4*)hidden)[t];
        for (int i = t; i < OUT_TOK; i += 192) out_mask[i] = 0.0f;
        if (t == 0) out_tome[0] = tome[0];
        return;
    }

    int j   = b;
    int cnt = g_cnt[j];
    int off = g_off[j];
    float inv = 1.0f / (1.0f + (float)cnt);

    float4 acc = ((const float4*)&hidden[(size_t)(2 * j + 1) * D_HID])[t];

    int s = 0;
    for (; s + 4 <= cnt; s += 4) {
        int i0 = g_list[off + s + 0];
        int i1 = g_list[off + s + 1];
        int i2 = g_list[off + s + 2];
        int i3 = g_list[off + s + 3];
        float4 v0 = ((const float4*)&hidden[(size_t)(2 * i0) * D_HID])[t];
        float4 v1 = ((const float4*)&hidden[(size_t)(2 * i1) * D_HID])[t];
        float4 v2 = ((const float4*)&hidden[(size_t)(2 * i2) * D_HID])[t];
        float4 v3 = ((const float4*)&hidden[(size_t)(2 * i3) * D_HID])[t];
        acc.x += v0.x + v1.x + v2.x + v3.x;
        acc.y += v0.y + v1.y + v2.y + v3.y;
        acc.z += v0.z + v1.z + v2.z + v3.z;
        acc.w += v0.w + v1.w + v2.w + v3.w;
    }
    for (; s < cnt; s++) {
        int i0 = g_list[off + s];
        float4 v0 = ((const float4*)&hidden[(size_t)(2 * i0) * D_HID])[t];
        acc.x += v0.x; acc.y += v0.y; acc.z += v0.z; acc.w += v0.w;
    }
    acc.x *= inv; acc.y *= inv; acc.z *= inv; acc.w *= inv;
    ((float4*)&out_tok[(size_t)(1 + j) * D_HID])[t] = acc;

    if (t == 0) {
        float ts = tome[2 * j + 1];
        for (int q = 0; q < cnt; q++) ts += tome[2 * g_list[off + q]];
        out_tome[1 + j] = ts;
    }
}

// ------------------------------------------------------------------------
extern "C" void kernel_launch(void* const* d_in, const int* in_sizes, int n_in,
                              void* d_out, int out_size) {
    const float* hidden = (const float*)d_in[0];
    const float* key    = (const float*)d_in[3];
    const float* tome   = (const float*)d_in[4];
    float* out = (float*)d_out;

    cudaFuncSetAttribute(k_argmax,
                         cudaFuncAttributeMaxDynamicSharedMemorySize, 65536);

    k_metric<<<512, 256>>>(key);
    k_argmax<<<dim3(M2 / BM, M2 / BM), 256, 65536>>>();
    k_merge<<<OUT_TOK, 192>>>(hidden, tome, out);
}

// round 13
// speedup vs baseline: 1.0686x; 1.0686x over previous
#include <cuda_runtime.h>
#include <cuda_bf16.h>
#include <cstdint>

// Problem constants (fixed shapes)
#define L_TOK   4096
#define D_HID   768
#define H_HEAD  12
#define DH      64
#define M2      2048          // L/2
#define OUT_TOK 2049          // 1 unmerged + 2048 dst

// ---------------- device scratch (no allocations allowed) ----------------
__device__ float              g_m[L_TOK * DH];      // normalized metric, 1 MB
__device__ unsigned long long g_best[M2];           // packed (score, ~col)
__device__ int                g_cnt[M2];            // #srcs per dst
__device__ int                g_off[M2];            // CSR offsets
__device__ int                g_list[M2];           // src rows grouped by dst

__device__ __forceinline__ unsigned sortable_f32(float f) {
    unsigned u = __float_as_uint(f);
    return (u & 0x80000000u) ? ~u : (u | 0x80000000u);
}
__device__ __forceinline__ unsigned long long pack2(float x) {
    unsigned long long r;
    asm("mov.b64 %0, {%1, %1};" : "=l"(r) : "f"(x));
    return r;
}
__device__ __forceinline__ void ffma2(unsigned long long& d,
                                      unsigned long long a,
                                      unsigned long long b) {
    asm("fma.rn.f32x2 %0, %1, %2, %0;" : "+l"(d) : "l"(a), "l"(b));
}

// ------------------------------------------------------------------------
// K1: metric = mean over heads of key_layer[0], L2-normalized per row.
// 2 warps per row (6 heads each), float2 loads. 8 rows per 512-thread block.
// grid: 512 x 512.  Also initializes g_best.
// ------------------------------------------------------------------------
__global__ __launch_bounds__(512) void k_metric(const float* __restrict__ key) {
    __shared__ float2 s_part[8][32];   // partial sums from odd-half warps

    int gtid = blockIdx.x * blockDim.x + threadIdx.x;
    if (gtid < M2 * 8 && (gtid & 7) == 0) g_best[gtid >> 3] = 0ull;  // 2048 inits spread out

    int t    = threadIdx.x;
    int pair = t >> 6;                 // 0..7 : row slot in block
    int half = (t >> 5) & 1;           // 0: heads 0-5, 1: heads 6-11
    int lane = t & 31;
    int row  = blockIdx.x * 8 + pair;  // 0..4095

    const float2* base = (const float2*)(key + (size_t)row * DH) + lane;
    const size_t hstride = (size_t)L_TOK * DH / 2;    // head stride in float2

    float2 v = make_float2(0.f, 0.f);
    #pragma unroll
    for (int h = 0; h < 6; h++) {
        float2 x = base[(size_t)(half * 6 + h) * hstride];
        v.x += x.x; v.y += x.y;
    }

    if (half == 1) s_part[pair][lane] = v;
    __syncthreads();

    if (half == 0) {
        float2 o = s_part[pair][lane];
        v.x += o.x; v.y += o.y;
        const float invH = 1.0f / (float)H_HEAD;
        v.x *= invH; v.y *= invH;
        float ss = v.x * v.x + v.y * v.y;
        #pragma unroll
        for (int o2 = 16; o2; o2 >>= 1) ss += __shfl_xor_sync(0xffffffffu, ss, o2);
        float r = rsqrtf(ss);
        r = r * (1.5f - 0.5f * ss * r * r);   // one Newton step
        v.x *= r; v.y *= r;
        ((float2*)(g_m + row * DH))[lane] = v;
    }
}

// ------------------------------------------------------------------------
// K2: argmax_j dot(a_i, b_j) — 2048x2048x64 fp32 GEMM with FFMA2.
// Tile 128x128, 256 threads, 8x8 microtile. A duplicated into (a,a) pairs
// in REGISTERS; B pairs reinterpreted from contiguous smem float4.
// 64 KB dynamic smem.  grid: (16, 16)
// ------------------------------------------------------------------------
#define BM 128
__global__ __launch_bounds__(256) void k_argmax() {
    extern __shared__ float smem[];
    float* As = smem;              // [64][128] K-major: As[k*128 + m]
    float* Bs = smem + 64 * BM;    // [64][128]

    int tid = threadIdx.x;
    int tx  = tid & 15;            // col group (8 cols each)
    int ty  = tid >> 4;            // row group (8 rows each)

    int aRow0 = blockIdx.y * BM;
    int bRow0 = blockIdx.x * BM;

    // Load tiles, transposing to K-major. 8 float4 per thread per matrix.
    int lm  = tid & 31;            // m within 32-row group
    int kq8 = tid >> 5;            // 0..7
    #pragma unroll
    for (int it = 0; it < 4; it++) {
        int m = it * 32 + lm;
        const float* arow = &g_m[(size_t)(2 * (aRow0 + m)) * DH];
        const float* brow = &g_m[(size_t)(2 * (bRow0 + m) + 1) * DH];
        #pragma unroll
        for (int half = 0; half < 2; half++) {
            int kq = kq8 + half * 8;           // 0..15
            float4 va = *(const float4*)&arow[kq * 4];
            float4 vb = *(const float4*)&brow[kq * 4];
            As[(kq * 4 + 0) * BM + m] = va.x;
            As[(kq * 4 + 1) * BM + m] = va.y;
            As[(kq * 4 + 2) * BM + m] = va.z;
            As[(kq * 4 + 3) * BM + m] = va.w;
            Bs[(kq * 4 + 0) * BM + m] = vb.x;
            Bs[(kq * 4 + 1) * BM + m] = vb.y;
            Bs[(kq * 4 + 2) * BM + m] = vb.z;
            Bs[(kq * 4 + 3) * BM + m] = vb.w;
        }
    }
    __syncthreads();

    unsigned long long acc2[8][4];
    #pragma unroll
    for (int r = 0; r < 8; r++)
        #pragma unroll
        for (int c = 0; c < 4; c++) acc2[r][c] = 0ull;

    #pragma unroll 8
    for (int k = 0; k < 64; k++) {
        float4 a0 = *(const float4*)&As[k * BM + ty * 8];
        float4 a1 = *(const float4*)&As[k * BM + ty * 8 + 4];
        ulonglong2 b01 = *(const ulonglong2*)&Bs[k * BM + tx * 8];      // (b0,b1),(b2,b3)
        ulonglong2 b23 = *(const ulonglong2*)&Bs[k * BM + tx * 8 + 4];  // (b4,b5),(b6,b7)
        unsigned long long ap[8];
        ap[0] = pack2(a0.x); ap[1] = pack2(a0.y);
        ap[2] = pack2(a0.z); ap[3] = pack2(a0.w);
        ap[4] = pack2(a1.x); ap[5] = pack2(a1.y);
        ap[6] = pack2(a1.z); ap[7] = pack2(a1.w);
        #pragma unroll
        for (int r = 0; r < 8; r++) {
            ffma2(acc2[r][0], ap[r], b01.x);
            ffma2(acc2[r][1], ap[r], b01.y);
            ffma2(acc2[r][2], ap[r], b23.x);
            ffma2(acc2[r][3], ap[r], b23.y);
        }
    }

    // Argmax epilogue: per a-row, reduce across the 16 tx threads (half-warp)
    #pragma unroll
    for (int r = 0; r < 8; r++) {
        int row = aRow0 + ty * 8 + r;
        unsigned long long key = 0ull;
        #pragma unroll
        for (int c2 = 0; c2 < 4; c2++) {
            unsigned lo, hi;
            asm("mov.b64 {%0, %1}, %2;" : "=r"(lo), "=r"(hi) : "l"(acc2[r][c2]));
            float s0 = __uint_as_float(lo), s1 = __uint_as_float(hi);
            int col0 = bRow0 + tx * 8 + 2 * c2;
            unsigned long long k0 =
                ((unsigned long long)sortable_f32(s0) << 32) | (unsigned)(~(unsigned)col0);
            unsigned long long k1 =
                ((unsigned long long)sortable_f32(s1) << 32) | (unsigned)(~(unsigned)(col0 + 1));
            if (k0 > key) key = k0;
            if (k1 > key) key = k1;
        }
        #pragma unroll
        for (int o = 8; o; o >>= 1) {
            unsigned long long other = __shfl_down_sync(0xffffffffu, key, o, 16);
            key = (other > key) ? other : key;
        }
        if (tx == 0) atomicMax(&g_best[row], key);
    }
}

// ------------------------------------------------------------------------
// K3: build CSR (counts, offsets, src lists).  1 block x 1024 threads.
// Warp-shuffle scan.
// ------------------------------------------------------------------------
__global__ __launch_bounds__(1024) void k_build() {
    __shared__ int s_cnt[M2];
    __shared__ int s_off[M2];
    __shared__ int s_wsum[32];
    int t    = threadIdx.x;
    int lane = t & 31;
    int wid  = t >> 5;
    int i0 = 2 * t, i1 = 2 * t + 1;

    s_cnt[i0] = 0; s_cnt[i1] = 0;
    __syncthreads();

    int dA = (int)(~(unsigned)g_best[i0]) & (M2 - 1);
    int dB = (int)(~(unsigned)g_best[i1]) & (M2 - 1);
    if (i0 >= 1) atomicAdd(&s_cnt[dA], 1);   // src row 0 is unmerged
    atomicAdd(&s_cnt[dB], 1);
    __syncthreads();

    int a = s_cnt[i0], b = s_cnt[i1];
    int pair = a + b;

    int v = pair;                            // inclusive warp scan
    #pragma unroll
    for (int o = 1; o < 32; o <<= 1) {
        int n = __shfl_up_sync(0xffffffffu, v, o);
        if (lane >= o) v += n;
    }
    if (lane == 31) s_wsum[wid] = v;
    __syncthreads();
    if (wid == 0) {
        int w = s_wsum[lane];
        #pragma unroll
        for (int o = 1; o < 32; o <<= 1) {
            int n = __shfl_up_sync(0xffffffffu, w, o);
            if (lane >= o) w += n;
        }
        s_wsum[lane] = w;
    }
    __syncthreads();
    int incl = v + ((wid > 0) ? s_wsum[wid - 1] : 0);
    int excl = incl - pair;

    s_off[i0] = excl;
    s_off[i1] = excl + a;
    g_cnt[i0] = a;  g_cnt[i1] = b;
    g_off[i0] = excl; g_off[i1] = excl + a;
    __syncthreads();

    s_cnt[i0] = s_off[i0]; s_cnt[i1] = s_off[i1];   // fill cursors
    __syncthreads();
    if (i0 >= 1) { int p = atomicAdd(&s_cnt[dA], 1); g_list[p] = i0; }
    {             int p = atomicAdd(&s_cnt[dB], 1); g_list[p] = i1; }
}

// ------------------------------------------------------------------------
// K4: gather-merge (best-measured R4 design).
// Block j < 2048: out row 1+j = (dst_row + sum srcs)/(1+cnt).
// Block 2048: unmerged row 0 + attention mask + tome[0].
// grid: 2049 x 192
// ------------------------------------------------------------------------
__global__ __launch_bounds__(192) void k_merge(const float* __restrict__ hidden,
                                               const float* __restrict__ tome,
                                               float* __restrict__ out) {
    float* out_tok  = out;                              // 2049 x 768
    float* out_mask = out + (size_t)OUT_TOK * D_HID;    // 2049
    float* out_tome = out_mask + OUT_TOK;               // 2049
    int b = blockIdx.x, t = threadIdx.x;

    if (b == M2) {   // unmerged row 0, mask, tome[0]
        ((float4*)out_tok)[t] = ((const float4*)hidden)[t];
        for (int i = t; i < OUT_TOK; i += 192) out_mask[i] = 0.0f;
        if (t == 0) out_tome[0] = tome[0];
        return;
    }

    int j   = b;
    int cnt = g_cnt[j];
    int off = g_off[j];
    float inv = 1.0f / (1.0f + (float)cnt);

    float4 acc = ((const float4*)&hidden[(size_t)(2 * j + 1) * D_HID])[t];

    int s = 0;
    for (; s + 4 <= cnt; s += 4) {
        int i0 = g_list[off + s + 0];
        int i1 = g_list[off + s + 1];
        int i2 = g_list[off + s + 2];
        int i3 = g_list[off + s + 3];
        float4 v0 = ((const float4*)&hidden[(size_t)(2 * i0) * D_HID])[t];
        float4 v1 = ((const float4*)&hidden[(size_t)(2 * i1) * D_HID])[t];
        float4 v2 = ((const float4*)&hidden[(size_t)(2 * i2) * D_HID])[t];
        float4 v3 = ((const float4*)&hidden[(size_t)(2 * i3) * D_HID])[t];
        acc.x += v0.x + v1.x + v2.x + v3.x;
        acc.y += v0.y + v1.y + v2.y + v3.y;
        acc.z += v0.z + v1.z + v2.z + v3.z;
        acc.w += v0.w + v1.w + v2.w + v3.w;
    }
    for (; s < cnt; s++) {
        int i0 = g_list[off + s];
        float4 v0 = ((const float4*)&hidden[(size_t)(2 * i0) * D_HID])[t];
        acc.x += v0.x; acc.y += v0.y; acc.z += v0.z; acc.w += v0.w;
    }
    acc.x *= inv; acc.y *= inv; acc.z *= inv; acc.w *= inv;
    ((float4*)&out_tok[(size_t)(1 + j) * D_HID])[t] = acc;

    if (t == 0) {
        float ts = tome[2 * j + 1];
        for (int q = 0; q < cnt; q++) ts += tome[2 * g_list[off + q]];
        out_tome[1 + j] = ts;
    }
}

// ------------------------------------------------------------------------
extern "C" void kernel_launch(void* const* d_in, const int* in_sizes, int n_in,
                              void* d_out, int out_size) {
    const float* hidden = (const float*)d_in[0];
    const float* key    = (const float*)d_in[3];
    const float* tome   = (const float*)d_in[4];
    float* out = (float*)d_out;

    cudaFuncSetAttribute(k_argmax,
                         cudaFuncAttributeMaxDynamicSharedMemorySize, 65536);

    k_metric<<<512, 512>>>(key);
    k_argmax<<<dim3(M2 / BM, M2 / BM), 256, 65536>>>();
    k_build<<<1, 1024>>>();
    k_merge<<<OUT_TOK, 192>>>(hidden, tome, out);
}